// round 9
// baseline (speedup 1.0000x reference)
#include <cuda_runtime.h>
#include <cuda_fp16.h>
#include <cstdint>

// ---------------------------------------------------------------------------
// IntentSlotLabellingModel on GB300 (sm_103a), Round 8:
// FP16 mma.sync mainloop, now 512-thread CTAs (4 warps/SMSP) for latency
// hiding: CTA tile 256xNT (NT=256 / 128), 16 warps 4m x 4n, warp tile
// 64x(NT/4). cp.async DEPTH=3 ring. Proven scalar-LDS fragment pattern.
//   gather+cvt -> GEMM1+ReLU -> GEMM2+ReLU -> GEMM3+bias
//   M=32768, E=512, C=512, H=1024, L=128.
// ---------------------------------------------------------------------------

#define BM 256
#define BK 64
#define DEPTH 3
#define SSTR_H 72                       // padded row stride in halves (144 B)
#define A_STH (BM * SSTR_H)             // 18432 halves / stage

__device__ __half g_A[32768L * 512];    // gathered fp16 embeddings
__device__ __half g_H[32768L * 512];    // post-conv relu (fp16)
__device__ __half g_Z[32768L * 1024];   // post-dec1 relu (fp16)
__device__ __half g_cw[512L * 512];     // conv_w  fp16 [N,K]
__device__ __half g_w1t[1024L * 512];   // dec_w1 -> fp16 [N,K]
__device__ __half g_w2t[128L * 1024];   // dec_w2 -> fp16 [N,K]

__device__ __forceinline__ uint32_t smem_u32(const void* p) {
    uint32_t a;
    asm("{ .reg .u64 t; cvta.to.shared.u64 t, %1; cvt.u32.u64 %0, t; }"
        : "=r"(a) : "l"(p));
    return a;
}
__device__ __forceinline__ void cp_async16(uint32_t dst, const void* src) {
    asm volatile("cp.async.cg.shared.global [%0], [%1], 16;"
                 :: "r"(dst), "l"(src) : "memory");
}
__device__ __forceinline__ void cp_commit() {
    asm volatile("cp.async.commit_group;" ::: "memory");
}
template <int N> __device__ __forceinline__ void cp_wait() {
    asm volatile("cp.async.wait_group %0;" :: "n"(N) : "memory");
}
__device__ __forceinline__ void mma_f16(float* d, const uint32_t* a, const uint32_t* b) {
    asm volatile(
        "mma.sync.aligned.m16n8k16.row.col.f32.f16.f16.f32 "
        "{%0,%1,%2,%3}, {%4,%5,%6,%7}, {%8,%9}, {%0,%1,%2,%3};"
        : "+f"(d[0]), "+f"(d[1]), "+f"(d[2]), "+f"(d[3])
        : "r"(a[0]), "r"(a[1]), "r"(a[2]), "r"(a[3]), "r"(b[0]), "r"(b[1]));
}

// ---------------------------------------------------------------------------
// GEMM: C[256 x NT tile] = A[M,K](f16) @ B[N,K](f16)^T + bias
// 512 threads, 16 warps: warp_m = (warp&3)*64, warp_n = (warp>>2)*(NT/4).
// ---------------------------------------------------------------------------
template <int NT, bool HALF_OUT>
__global__ void __launch_bounds__(512, 1)
mma_gemm(const __half* __restrict__ A, const __half* __restrict__ B,
         const float* __restrict__ bias, void* __restrict__ Cv,
         int N, int K)
{
    constexpr int B_STH  = NT * SSTR_H;
    constexpr int STG_H  = A_STH + B_STH;
    constexpr int WN     = NT / 4;          // warp n-extent: 64 or 32
    constexpr int NTILES = WN / 8;          // 8 or 4
    constexpr int BTASK  = NT * 8 / 512;    // 4 or 2

    extern __shared__ __half smem[];
    const uint32_t sbase = smem_u32(smem);

    const int tid  = threadIdx.x;
    const int lane = tid & 31;
    const int warp = tid >> 5;
    const int warp_m = (warp & 3) * 64;      // 0,64,128,192
    const int warp_n = (warp >> 2) * WN;     // 4 n-positions
    const int gr = lane >> 2;                // 0..7
    const int gc = lane & 3;                 // 0..3

    const int  n0 = blockIdx.x * NT;
    const long m0 = (long)blockIdx.y * BM;

    // producer tasks (512 threads): A 4 x cp16, B BTASK x cp16
    const __half* a_src[4]; uint32_t a_dst[4];
    #pragma unroll
    for (int i = 0; i < 4; i++) {
        int idx = tid + i * 512;             // 0..2047
        int r   = idx >> 3;                  // 0..255
        int c8  = (idx & 7) * 8;             // 0..56 halves
        a_src[i] = A + (m0 + r) * (long)K + c8;
        a_dst[i] = sbase + (uint32_t)(r * SSTR_H + c8) * 2u;
    }
    const __half* b_src[BTASK]; uint32_t b_dst[BTASK];
    #pragma unroll
    for (int i = 0; i < BTASK; i++) {
        int idx = tid + i * 512;
        int r   = idx >> 3;                  // 0..NT-1
        int c8  = (idx & 7) * 8;
        b_src[i] = B + (long)(n0 + r) * (long)K + c8;
        b_dst[i] = sbase + (uint32_t)(A_STH + r * SSTR_H + c8) * 2u;
    }

    const int S = K / BK;

    auto issue = [&](int s) {
        const uint32_t so = (uint32_t)((s % DEPTH) * STG_H * 2);
        const int k0 = s * BK;
        #pragma unroll
        for (int i = 0; i < 4; i++)
            cp_async16(a_dst[i] + so, a_src[i] + k0);
        #pragma unroll
        for (int i = 0; i < BTASK; i++)
            cp_async16(b_dst[i] + so, b_src[i] + k0);
    };

    issue(0); cp_commit();
    issue(1); cp_commit();

    float acc[4][NTILES][4];
    #pragma unroll
    for (int mt = 0; mt < 4; mt++)
        #pragma unroll
        for (int nt = 0; nt < NTILES; nt++)
            #pragma unroll
            for (int r = 0; r < 4; r++)
                acc[mt][nt][r] = 0.0f;

    for (int s = 0; s < S; s++) {
        cp_wait<DEPTH - 2>();
        __syncthreads();
        if (s + 2 < S) issue(s + 2);
        cp_commit();

        const __half* As = smem + (s % DEPTH) * STG_H;
        const __half* Bs = As + A_STH;

        #pragma unroll
        for (int ks = 0; ks < BK; ks += 16) {
            uint32_t af[4][4], bf[NTILES][2];
            #pragma unroll
            for (int mt = 0; mt < 4; mt++) {
                int r = (warp_m + mt * 16 + gr) * SSTR_H + ks + gc * 2;
                af[mt][0] = *reinterpret_cast<const uint32_t*>(&As[r]);
                af[mt][1] = *reinterpret_cast<const uint32_t*>(&As[r + 8 * SSTR_H]);
                af[mt][2] = *reinterpret_cast<const uint32_t*>(&As[r + 8]);
                af[mt][3] = *reinterpret_cast<const uint32_t*>(&As[r + 8 * SSTR_H + 8]);
            }
            #pragma unroll
            for (int nt = 0; nt < NTILES; nt++) {
                int r = (warp_n + nt * 8 + gr) * SSTR_H + ks + gc * 2;
                bf[nt][0] = *reinterpret_cast<const uint32_t*>(&Bs[r]);
                bf[nt][1] = *reinterpret_cast<const uint32_t*>(&Bs[r + 8]);
            }
            #pragma unroll
            for (int mt = 0; mt < 4; mt++)
                #pragma unroll
                for (int nt = 0; nt < NTILES; nt++)
                    mma_f16(acc[mt][nt], af[mt], bf[nt]);
        }
    }

    // ---- epilogue ----
    #pragma unroll
    for (int nt = 0; nt < NTILES; nt++) {
        int n = n0 + warp_n + nt * 8 + gc * 2;
        float bb0 = bias[n], bb1 = bias[n + 1];
        #pragma unroll
        for (int mt = 0; mt < 4; mt++) {
            long m = m0 + warp_m + mt * 16 + gr;
            float x0 = acc[mt][nt][0] + bb0, x1 = acc[mt][nt][1] + bb1;
            float x2 = acc[mt][nt][2] + bb0, x3 = acc[mt][nt][3] + bb1;
            if (HALF_OUT) {
                __half* C = (__half*)Cv;
                __half2 h0 = __floats2half2_rn(fmaxf(x0, 0.0f), fmaxf(x1, 0.0f));
                __half2 h1 = __floats2half2_rn(fmaxf(x2, 0.0f), fmaxf(x3, 0.0f));
                *reinterpret_cast<__half2*>(C + m * (long)N + n)       = h0;
                *reinterpret_cast<__half2*>(C + (m + 8) * (long)N + n) = h1;
            } else {
                float* C = (float*)Cv;
                *reinterpret_cast<float2*>(C + m * (long)N + n)       = make_float2(x0, x1);
                *reinterpret_cast<float2*>(C + (m + 8) * (long)N + n) = make_float2(x2, x3);
            }
        }
    }
}

// ---------------------------------------------------------------------------
// Pre-pass kernels
// ---------------------------------------------------------------------------
__global__ void gather_cvt(const float* __restrict__ emb,
                           const int* __restrict__ tok,
                           __half* __restrict__ out)
{
    long i = (long)blockIdx.x * blockDim.x + threadIdx.x;   // float4 index
    int m = (int)(i >> 7);
    int c = (int)(i & 127) * 4;
    const float4 v = *reinterpret_cast<const float4*>(emb + (long)tok[m] * 512 + c);
    *reinterpret_cast<__half2*>(out + (long)m * 512 + c)     = __floats2half2_rn(v.x, v.y);
    *reinterpret_cast<__half2*>(out + (long)m * 512 + c + 2) = __floats2half2_rn(v.z, v.w);
}

__device__ __forceinline__ void tile_transpose_cvt(
    const float* __restrict__ in, __half* __restrict__ out,
    int K, int N, int bx, int by, int tid)
{
    __shared__ float t[32][33];
    int n0 = bx * 32, k0 = by * 32;
    int x = tid & 31, y = tid >> 5;       // 32 x 8
    #pragma unroll
    for (int i = 0; i < 32; i += 8)
        t[y + i][x] = in[(long)(k0 + y + i) * N + n0 + x];
    __syncthreads();
    #pragma unroll
    for (int i = 0; i < 32; i += 8)
        out[(long)(n0 + y + i) * K + k0 + x] = __float2half_rn(t[x][y + i]);
}

__global__ void prep_weights(const float* __restrict__ w1, __half* __restrict__ w1t,
                             const float* __restrict__ w2, __half* __restrict__ w2t,
                             const float* __restrict__ cw, __half* __restrict__ cwh)
{
    const int b = blockIdx.x;
    const int tid = threadIdx.x;
    if (b < 512) {
        tile_transpose_cvt(w1, w1t, 512, 1024, b & 31, b >> 5, tid);
    } else if (b < 640) {
        int bb = b - 512;
        tile_transpose_cvt(w2, w2t, 1024, 128, bb & 3, bb >> 2, tid);
    } else {
        long i = ((long)(b - 640) * 256 + tid) * 4;
        const float4 v = *reinterpret_cast<const float4*>(cw + i);
        *reinterpret_cast<__half2*>(cwh + i)     = __floats2half2_rn(v.x, v.y);
        *reinterpret_cast<__half2*>(cwh + i + 2) = __floats2half2_rn(v.z, v.w);
    }
}

extern "C" void kernel_launch(void* const* d_in, const int* in_sizes, int n_in,
                              void* d_out, int out_size)
{
    const int*   tokens = (const int*)  d_in[0];
    const float* emb    = (const float*)d_in[1];
    const float* conv_w = (const float*)d_in[2];
    const float* conv_b = (const float*)d_in[3];
    const float* w1     = (const float*)d_in[4];
    const float* b1     = (const float*)d_in[5];
    const float* w2     = (const float*)d_in[6];
    const float* b2     = (const float*)d_in[7];
    float* out = (float*)d_out;

    const int M = in_sizes[0];   // 32768

    __half *A, *H, *Z, *CW, *W1T, *W2T;
    cudaGetSymbolAddress((void**)&A,   g_A);
    cudaGetSymbolAddress((void**)&H,   g_H);
    cudaGetSymbolAddress((void**)&Z,   g_Z);
    cudaGetSymbolAddress((void**)&CW,  g_cw);
    cudaGetSymbolAddress((void**)&W1T, g_w1t);
    cudaGetSymbolAddress((void**)&W2T, g_w2t);

    gather_cvt<<<(int)((long)M * 128 / 256), 256>>>(emb, tokens, A);
    prep_weights<<<896, 256>>>(w1, W1T, w2, W2T, conv_w, CW);

    const int SMEM256 = DEPTH * (A_STH + 256 * SSTR_H) * 2;  // 221184
    const int SMEM128 = DEPTH * (A_STH + 128 * SSTR_H) * 2;  // 165888
    cudaFuncSetAttribute(mma_gemm<256, true>,
                         cudaFuncAttributeMaxDynamicSharedMemorySize, SMEM256);
    cudaFuncSetAttribute(mma_gemm<128, false>,
                         cudaFuncAttributeMaxDynamicSharedMemorySize, SMEM128);

    const int MB = M / BM;   // 128

    // L1: H = half(relu(A @ CW^T + conv_b))             [M, 512]
    mma_gemm<256, true><<<dim3(512 / 256, MB), 512, SMEM256>>>(A, CW, conv_b, H, 512, 512);

    // L2: Z = half(relu(H @ W1T^T + b1))                [M, 1024]
    mma_gemm<256, true><<<dim3(1024 / 256, MB), 512, SMEM256>>>(H, W1T, b1, Z, 1024, 512);

    // L3: out = Z @ W2T^T + b2                          [M, 128]
    mma_gemm<128, false><<<dim3(128 / 128, MB), 512, SMEM128>>>(Z, W2T, b2, out, 128, 1024);
}

// round 10
// speedup vs baseline: 2.2155x; 2.2155x over previous
#include <cuda_runtime.h>
#include <cuda_fp16.h>
#include <cstdint>

// ---------------------------------------------------------------------------
// IntentSlotLabellingModel on GB300 (sm_103a), Round 9:
// FP16 mma.sync, 2 CTAs/SM for real latency hiding (R8's 512-thr variant
// spilled: 128-reg cap < 128 acc regs). CTA 128x128, 256 thr, 8 warps
// (2m x 4n), warp tile 64x32 -> ~118 regs, no spill. DEPTH=3 cp.async.
//   gather+cvt -> GEMM1+ReLU -> GEMM2+ReLU -> GEMM3+bias
//   M=32768, E=512, C=512, H=1024, L=128.
// ---------------------------------------------------------------------------

#define BM 128
#define BN 128
#define BK 64
#define DEPTH 3
#define SSTR_H 72                       // padded row stride in halves (144 B)
#define A_STH (BM * SSTR_H)             // 9216 halves / stage
#define B_STH (BN * SSTR_H)             // 9216 halves / stage
#define STG_H (A_STH + B_STH)           // 18432 halves / stage
#define SMEM_BYTES (DEPTH * STG_H * 2)  // 110592 B -> 2 CTAs/SM

__device__ __half g_A[32768L * 512];    // gathered fp16 embeddings
__device__ __half g_H[32768L * 512];    // post-conv relu (fp16)
__device__ __half g_Z[32768L * 1024];   // post-dec1 relu (fp16)
__device__ __half g_cw[512L * 512];     // conv_w  fp16 [N,K]
__device__ __half g_w1t[1024L * 512];   // dec_w1 -> fp16 [N,K]
__device__ __half g_w2t[128L * 1024];   // dec_w2 -> fp16 [N,K]

__device__ __forceinline__ uint32_t smem_u32(const void* p) {
    uint32_t a;
    asm("{ .reg .u64 t; cvta.to.shared.u64 t, %1; cvt.u32.u64 %0, t; }"
        : "=r"(a) : "l"(p));
    return a;
}
__device__ __forceinline__ void cp_async16(uint32_t dst, const void* src) {
    asm volatile("cp.async.cg.shared.global [%0], [%1], 16;"
                 :: "r"(dst), "l"(src) : "memory");
}
__device__ __forceinline__ void cp_commit() {
    asm volatile("cp.async.commit_group;" ::: "memory");
}
template <int N> __device__ __forceinline__ void cp_wait() {
    asm volatile("cp.async.wait_group %0;" :: "n"(N) : "memory");
}
__device__ __forceinline__ void mma_f16(float* d, const uint32_t* a, const uint32_t* b) {
    asm volatile(
        "mma.sync.aligned.m16n8k16.row.col.f32.f16.f16.f32 "
        "{%0,%1,%2,%3}, {%4,%5,%6,%7}, {%8,%9}, {%0,%1,%2,%3};"
        : "+f"(d[0]), "+f"(d[1]), "+f"(d[2]), "+f"(d[3])
        : "r"(a[0]), "r"(a[1]), "r"(a[2]), "r"(a[3]), "r"(b[0]), "r"(b[1]));
}

// ---------------------------------------------------------------------------
// GEMM: C[128 x 128 tile] = A[M,K](f16) @ B[N,K](f16)^T + bias
// 8 warps: warp_m = (warp>>2)*64, warp_n = (warp&3)*32. Warp tile 64x32.
// ---------------------------------------------------------------------------
template <bool HALF_OUT>
__global__ void __launch_bounds__(256, 2)
mma_gemm(const __half* __restrict__ A, const __half* __restrict__ B,
         const float* __restrict__ bias, void* __restrict__ Cv,
         int N, int K)
{
    extern __shared__ __half smem[];
    const uint32_t sbase = smem_u32(smem);

    const int tid  = threadIdx.x;
    const int lane = tid & 31;
    const int warp = tid >> 5;
    const int warp_m = (warp >> 2) * 64;     // 0,64
    const int warp_n = (warp & 3) * 32;      // 0,32,64,96
    const int gr = lane >> 2;                // 0..7
    const int gc = lane & 3;                 // 0..3

    const int  n0 = blockIdx.x * BN;
    const long m0 = (long)blockIdx.y * BM;

    // producer: 4 A-tasks + 4 B-tasks per thread, single base + const stride
    const int r0 = tid >> 3;                 // 0..31
    const int c8 = (tid & 7) * 8;            // 0..56 halves
    const __half* a_base = A + (m0 + r0) * (long)K + c8;
    const __half* b_base = B + (long)(n0 + r0) * (long)K + c8;
    const uint32_t a_dst0 = sbase + (uint32_t)(r0 * SSTR_H + c8) * 2u;
    const uint32_t b_dst0 = sbase + (uint32_t)(A_STH + r0 * SSTR_H + c8) * 2u;
    const long  g_step = 32L * K;            // 32 rows in gmem (halves)
    const uint32_t s_step = 32u * SSTR_H * 2u;  // 32 rows in smem (bytes)

    const int S = K / BK;

    auto issue = [&](int s) {
        const uint32_t so = (uint32_t)((s % DEPTH) * STG_H * 2);
        const int k0 = s * BK;
        #pragma unroll
        for (int i = 0; i < 4; i++)
            cp_async16(a_dst0 + so + i * s_step, a_base + k0 + i * g_step);
        #pragma unroll
        for (int i = 0; i < 4; i++)
            cp_async16(b_dst0 + so + i * s_step, b_base + k0 + i * g_step);
    };

    issue(0); cp_commit();
    issue(1); cp_commit();

    float acc[4][4][4];
    #pragma unroll
    for (int mt = 0; mt < 4; mt++)
        #pragma unroll
        for (int nt = 0; nt < 4; nt++)
            #pragma unroll
            for (int r = 0; r < 4; r++)
                acc[mt][nt][r] = 0.0f;

    for (int s = 0; s < S; s++) {
        cp_wait<DEPTH - 2>();
        __syncthreads();
        if (s + 2 < S) issue(s + 2);
        cp_commit();

        const __half* As = smem + (s % DEPTH) * STG_H;
        const __half* Bs = As + A_STH;

        #pragma unroll
        for (int ks = 0; ks < BK; ks += 16) {
            uint32_t af[4][4], bf[4][2];
            #pragma unroll
            for (int mt = 0; mt < 4; mt++) {
                int r = (warp_m + mt * 16 + gr) * SSTR_H + ks + gc * 2;
                af[mt][0] = *reinterpret_cast<const uint32_t*>(&As[r]);
                af[mt][1] = *reinterpret_cast<const uint32_t*>(&As[r + 8 * SSTR_H]);
                af[mt][2] = *reinterpret_cast<const uint32_t*>(&As[r + 8]);
                af[mt][3] = *reinterpret_cast<const uint32_t*>(&As[r + 8 * SSTR_H + 8]);
            }
            #pragma unroll
            for (int nt = 0; nt < 4; nt++) {
                int r = (warp_n + nt * 8 + gr) * SSTR_H + ks + gc * 2;
                bf[nt][0] = *reinterpret_cast<const uint32_t*>(&Bs[r]);
                bf[nt][1] = *reinterpret_cast<const uint32_t*>(&Bs[r + 8]);
            }
            #pragma unroll
            for (int mt = 0; mt < 4; mt++)
                #pragma unroll
                for (int nt = 0; nt < 4; nt++)
                    mma_f16(acc[mt][nt], af[mt], bf[nt]);
        }
    }

    // ---- epilogue ----
    #pragma unroll
    for (int nt = 0; nt < 4; nt++) {
        int n = n0 + warp_n + nt * 8 + gc * 2;
        float bb0 = bias[n], bb1 = bias[n + 1];
        #pragma unroll
        for (int mt = 0; mt < 4; mt++) {
            long m = m0 + warp_m + mt * 16 + gr;
            float x0 = acc[mt][nt][0] + bb0, x1 = acc[mt][nt][1] + bb1;
            float x2 = acc[mt][nt][2] + bb0, x3 = acc[mt][nt][3] + bb1;
            if (HALF_OUT) {
                __half* C = (__half*)Cv;
                __half2 h0 = __floats2half2_rn(fmaxf(x0, 0.0f), fmaxf(x1, 0.0f));
                __half2 h1 = __floats2half2_rn(fmaxf(x2, 0.0f), fmaxf(x3, 0.0f));
                *reinterpret_cast<__half2*>(C + m * (long)N + n)       = h0;
                *reinterpret_cast<__half2*>(C + (m + 8) * (long)N + n) = h1;
            } else {
                float* C = (float*)Cv;
                *reinterpret_cast<float2*>(C + m * (long)N + n)       = make_float2(x0, x1);
                *reinterpret_cast<float2*>(C + (m + 8) * (long)N + n) = make_float2(x2, x3);
            }
        }
    }
}

// ---------------------------------------------------------------------------
// Pre-pass kernels (unchanged, proven)
// ---------------------------------------------------------------------------
__global__ void gather_cvt(const float* __restrict__ emb,
                           const int* __restrict__ tok,
                           __half* __restrict__ out)
{
    long i = (long)blockIdx.x * blockDim.x + threadIdx.x;   // float4 index
    int m = (int)(i >> 7);
    int c = (int)(i & 127) * 4;
    const float4 v = *reinterpret_cast<const float4*>(emb + (long)tok[m] * 512 + c);
    *reinterpret_cast<__half2*>(out + (long)m * 512 + c)     = __floats2half2_rn(v.x, v.y);
    *reinterpret_cast<__half2*>(out + (long)m * 512 + c + 2) = __floats2half2_rn(v.z, v.w);
}

__device__ __forceinline__ void tile_transpose_cvt(
    const float* __restrict__ in, __half* __restrict__ out,
    int K, int N, int bx, int by, int tid)
{
    __shared__ float t[32][33];
    int n0 = bx * 32, k0 = by * 32;
    int x = tid & 31, y = tid >> 5;       // 32 x 8
    #pragma unroll
    for (int i = 0; i < 32; i += 8)
        t[y + i][x] = in[(long)(k0 + y + i) * N + n0 + x];
    __syncthreads();
    #pragma unroll
    for (int i = 0; i < 32; i += 8)
        out[(long)(n0 + y + i) * K + k0 + x] = __float2half_rn(t[x][y + i]);
}

__global__ void prep_weights(const float* __restrict__ w1, __half* __restrict__ w1t,
                             const float* __restrict__ w2, __half* __restrict__ w2t,
                             const float* __restrict__ cw, __half* __restrict__ cwh)
{
    const int b = blockIdx.x;
    const int tid = threadIdx.x;
    if (b < 512) {
        tile_transpose_cvt(w1, w1t, 512, 1024, b & 31, b >> 5, tid);
    } else if (b < 640) {
        int bb = b - 512;
        tile_transpose_cvt(w2, w2t, 1024, 128, bb & 3, bb >> 2, tid);
    } else {
        long i = ((long)(b - 640) * 256 + tid) * 4;
        const float4 v = *reinterpret_cast<const float4*>(cw + i);
        *reinterpret_cast<__half2*>(cwh + i)     = __floats2half2_rn(v.x, v.y);
        *reinterpret_cast<__half2*>(cwh + i + 2) = __floats2half2_rn(v.z, v.w);
    }
}

extern "C" void kernel_launch(void* const* d_in, const int* in_sizes, int n_in,
                              void* d_out, int out_size)
{
    const int*   tokens = (const int*)  d_in[0];
    const float* emb    = (const float*)d_in[1];
    const float* conv_w = (const float*)d_in[2];
    const float* conv_b = (const float*)d_in[3];
    const float* w1     = (const float*)d_in[4];
    const float* b1     = (const float*)d_in[5];
    const float* w2     = (const float*)d_in[6];
    const float* b2     = (const float*)d_in[7];
    float* out = (float*)d_out;

    const int M = in_sizes[0];   // 32768

    __half *A, *H, *Z, *CW, *W1T, *W2T;
    cudaGetSymbolAddress((void**)&A,   g_A);
    cudaGetSymbolAddress((void**)&H,   g_H);
    cudaGetSymbolAddress((void**)&Z,   g_Z);
    cudaGetSymbolAddress((void**)&CW,  g_cw);
    cudaGetSymbolAddress((void**)&W1T, g_w1t);
    cudaGetSymbolAddress((void**)&W2T, g_w2t);

    gather_cvt<<<(int)((long)M * 128 / 256), 256>>>(emb, tokens, A);
    prep_weights<<<896, 256>>>(w1, W1T, w2, W2T, conv_w, CW);

    cudaFuncSetAttribute(mma_gemm<true>,
                         cudaFuncAttributeMaxDynamicSharedMemorySize, SMEM_BYTES);
    cudaFuncSetAttribute(mma_gemm<false>,
                         cudaFuncAttributeMaxDynamicSharedMemorySize, SMEM_BYTES);

    const int MB = M / BM;   // 256

    // L1: H = half(relu(A @ CW^T + conv_b))             [M, 512]
    mma_gemm<true><<<dim3(512 / BN, MB), 256, SMEM_BYTES>>>(A, CW, conv_b, H, 512, 512);

    // L2: Z = half(relu(H @ W1T^T + b1))                [M, 1024]
    mma_gemm<true><<<dim3(1024 / BN, MB), 256, SMEM_BYTES>>>(H, W1T, b1, Z, 1024, 512);

    // L3: out = Z @ W2T^T + b2                          [M, 128]
    mma_gemm<false><<<dim3(128 / BN, MB), 256, SMEM_BYTES>>>(Z, W2T, b2, out, 128, 1024);
}